// round 11
// baseline (speedup 1.0000x reference)
#include <cuda_runtime.h>
#include <cuda_bf16.h>
#include <cstdint>
#include <math.h>

#define BB 16
#define CC 128
#define TT 16384
#define KSPLIT 8
#define KRANGE (TT / KSPLIT)      // 2048 floats per CTA K-range
#define KT 64                     // K per smem tile (64 bf16 = 128B rows)
#define NKT (KRANGE / KT)         // 32 tiles
#define NG 3
#define NJOBS (BB * NG * KSPLIT)  // 384 CTAs

#define TILE_BYTES 16384          // 128 rows x 64 bf16
#define STAGE_BYTES 32768         // A + B tile
#define EPI_LANE 528              // padded per-lane epilogue bytes (32 float4 + pad)
#define EPI_WARP (32 * EPI_LANE)  // 16896
#define DYN_SMEM (4 * EPI_WARP)   // 67584 >= 2*STAGE_BYTES (65536)

#define NTAIL 384                 // tail blocks: (b,g) x 8 sixteen-row slices

// Scratch (no device allocations allowed -> globals)
__device__ float g_gram[(size_t)KSPLIT * BB * NG * CC * CC];   // 25 MB partials
__device__ float g_psum[NTAIL];
__device__ int   g_counter;       // zero-init; last tail block resets

__device__ __forceinline__ uint32_t smem_u32(const void* p) {
    return (uint32_t)__cvta_generic_to_shared(p);
}
__device__ __forceinline__ uint32_t swz(uint32_t off) {
    return off ^ ((off >> 3) & 0x70);   // SW128 for 128B rows
}
__device__ __forceinline__ void ldsm4(uint32_t& r0, uint32_t& r1, uint32_t& r2,
                                      uint32_t& r3, uint32_t addr) {
    asm volatile("ldmatrix.sync.aligned.m8n8.x4.shared.b16 {%0,%1,%2,%3}, [%4];"
                 : "=r"(r0), "=r"(r1), "=r"(r2), "=r"(r3) : "r"(addr));
}
__device__ __forceinline__ void mma16816(float* c, const uint32_t* a,
                                         uint32_t b0, uint32_t b1) {
    asm volatile(
        "mma.sync.aligned.m16n8k16.row.col.f32.bf16.bf16.f32 "
        "{%0,%1,%2,%3}, {%4,%5,%6,%7}, {%8,%9}, {%0,%1,%2,%3};"
        : "+f"(c[0]), "+f"(c[1]), "+f"(c[2]), "+f"(c[3])
        : "r"(a[0]), "r"(a[1]), "r"(a[2]), "r"(a[3]), "r"(b0), "r"(b1));
}
__device__ __forceinline__ uint2 cvt_bf16x4(float4 v) {
    __nv_bfloat162 lo = __floats2bfloat162_rn(v.x, v.y);
    __nv_bfloat162 hi = __floats2bfloat162_rn(v.z, v.w);
    return make_uint2(*(uint32_t*)&lo, *(uint32_t*)&hi);
}

// ---------------------------------------------------------------------------
// Gram kernel: one CTA per (b, gram, ksplit). 256 threads = 8 warps, ALL
// homogeneous (every warp MMAs, every thread loads — the proven config).
// Split-K consumer layout: 4 output positions (64x64) x 2 K-groups; K-group
// kg computes k16 steps {2kg, 2kg+1} of each KT=64 tile into private
// accumulators -> LDSM duplication drops from 96KB to 64KB per tile while
// keeping 2 MMA warps per SMSP. Pairs merge via smem once at the end.
// ---------------------------------------------------------------------------
extern "C" __global__ void __launch_bounds__(256, 1)
gram_kernel(const float* __restrict__ fs, const float* __restrict__ ft) {
    extern __shared__ char smem[];
    const uint32_t smb = smem_u32(smem);

    int bx  = blockIdx.x;
    int b   = bx / (NG * KSPLIT);
    int rem = bx % (NG * KSPLIT);
    int g   = rem / KSPLIT;
    int ks  = rem % KSPLIT;
    bool dual = (g == 2);

    const float* Am = (g == 0) ? ft : fs;
    const float* Bm = (g == 1) ? fs : ft;

    int tid  = threadIdx.x;
    int wid  = tid >> 5;
    int lane = tid & 31;

    // consumer mapping: 64x64 warp tile, split-K pair
    int kg  = wid >> 2;            // K-group 0/1
    int w4  = wid & 3;
    int wm  = w4 & 1;
    int wn  = w4 >> 1;
    int gid  = lane >> 2;
    int tid4 = lane & 3;
    uint32_t a_row  = (uint32_t)(wm * 64 + (lane & 15));
    uint32_t a_koff = (uint32_t)((lane >> 4) * 16);
    uint32_t b_rowbase = (uint32_t)(wn * 64 + ((lane >> 4) << 3) + (lane & 7));
    uint32_t b_koff = (uint32_t)(((lane >> 3) & 1) * 16);

    // loader mapping: 16 threads per 256B row segment; rows lrow0 + i*16
    int lrow0 = tid >> 4;          // 0..15
    int lcol  = tid & 15;
    const float* baseA = Am + (size_t)b * CC * TT + ks * KRANGE + (size_t)lcol * 4;
    const float* baseB = Bm + (size_t)b * CC * TT + ks * KRANGE + (size_t)lcol * 4;

    float acc[4][8][4];
#pragma unroll
    for (int mi = 0; mi < 4; mi++)
#pragma unroll
        for (int ni = 0; ni < 8; ni++)
#pragma unroll
            for (int q = 0; q < 4; q++) acc[mi][ni][q] = 0.f;

    // ---- prologue: tile 0 into buf 0 (chunked) ----
#pragma unroll
    for (int h = 0; h < 2; h++) {
        float4 va[4], vb[4];
#pragma unroll
        for (int i = 0; i < 4; i++)
            va[i] = *(const float4*)(baseA + (size_t)(lrow0 + (h * 4 + i) * 16) * TT);
        if (dual) {
#pragma unroll
            for (int i = 0; i < 4; i++)
                vb[i] = *(const float4*)(baseB + (size_t)(lrow0 + (h * 4 + i) * 16) * TT);
        }
#pragma unroll
        for (int i = 0; i < 4; i++) {
            uint32_t so = swz((uint32_t)(lrow0 + (h * 4 + i) * 16) * 128 + lcol * 8);
            *(uint2*)(smem + so) = cvt_bf16x4(va[i]);
        }
        if (dual) {
#pragma unroll
            for (int i = 0; i < 4; i++) {
                uint32_t so = swz((uint32_t)(lrow0 + (h * 4 + i) * 16) * 128 + lcol * 8);
                *(uint2*)(smem + TILE_BYTES + so) = cvt_bf16x4(vb[i]);
            }
        }
    }
    __syncthreads();

    for (int kt = 0; kt < NKT; kt++) {
        int cur = kt & 1;
        int nxt = cur ^ 1;
        bool pf = (kt + 1 < NKT);
        const float* pA = baseA + (size_t)(kt + 1) * KT;
        const float* pB = baseB + (size_t)(kt + 1) * KT;
        char* sdst = smem + nxt * STAGE_BYTES;

        uint32_t abase = smb + cur * STAGE_BYTES;
        uint32_t bbase = abase + (dual ? TILE_BYTES : 0);

#pragma unroll
        for (int h = 0; h < 2; h++) {
            // issue chunk-h loads of next tile
            float4 va[4], vb[4];
            if (pf) {
#pragma unroll
                for (int i = 0; i < 4; i++)
                    va[i] = *(const float4*)(pA + (size_t)(lrow0 + (h * 4 + i) * 16) * TT);
                if (dual) {
#pragma unroll
                    for (int i = 0; i < 4; i++)
                        vb[i] = *(const float4*)(pB + (size_t)(lrow0 + (h * 4 + i) * 16) * TT);
                }
            }

            // compute this K-group's k16 step for chunk h: kc = kg*2 + h
            {
                uint32_t kb = (uint32_t)((kg * 2 + h) * 32);
                uint32_t afr[4][4];
#pragma unroll
                for (int mi = 0; mi < 4; mi++) {
                    uint32_t addr = abase + swz((a_row + mi * 16) * 128 + kb + a_koff);
                    ldsm4(afr[mi][0], afr[mi][1], afr[mi][2], afr[mi][3], addr);
                }
#pragma unroll
                for (int nb = 0; nb < 4; nb++) {
                    uint32_t r0, r1, r2, r3;
                    uint32_t addr = bbase + swz((b_rowbase + nb * 16) * 128 + kb + b_koff);
                    ldsm4(r0, r1, r2, r3, addr);
#pragma unroll
                    for (int mi = 0; mi < 4; mi++) {
                        mma16816(acc[mi][2 * nb],     afr[mi], r0, r1);
                        mma16816(acc[mi][2 * nb + 1], afr[mi], r2, r3);
                    }
                }
            }

            // convert + store chunk h of next tile
            if (pf) {
#pragma unroll
                for (int i = 0; i < 4; i++) {
                    uint32_t so = swz((uint32_t)(lrow0 + (h * 4 + i) * 16) * 128 + lcol * 8);
                    *(uint2*)(sdst + so) = cvt_bf16x4(va[i]);
                }
                if (dual) {
#pragma unroll
                    for (int i = 0; i < 4; i++) {
                        uint32_t so = swz((uint32_t)(lrow0 + (h * 4 + i) * 16) * 128 + lcol * 8);
                        *(uint2*)(sdst + TILE_BYTES + so) = cvt_bf16x4(vb[i]);
                    }
                }
            }
        }
        __syncthreads();
    }

    // ---- epilogue: merge K-group pairs via smem (tile bufs now free) ----
    if (kg == 1) {
        char* ep = smem + w4 * EPI_WARP + lane * EPI_LANE;
#pragma unroll
        for (int mi = 0; mi < 4; mi++)
#pragma unroll
            for (int ni = 0; ni < 8; ni++)
                *(float4*)(ep + (mi * 8 + ni) * 16) =
                    make_float4(acc[mi][ni][0], acc[mi][ni][1],
                                acc[mi][ni][2], acc[mi][ni][3]);
    }
    __syncthreads();
    if (kg == 0) {
        char* ep = smem + w4 * EPI_WARP + lane * EPI_LANE;
        float* out = g_gram + (((size_t)ks * BB + b) * NG + g) * (CC * CC);
#pragma unroll
        for (int mi = 0; mi < 4; mi++) {
            int r0 = wm * 64 + mi * 16 + gid;
#pragma unroll
            for (int ni = 0; ni < 8; ni++) {
                float4 p = *(float4*)(ep + (mi * 8 + ni) * 16);
                int c0 = wn * 64 + ni * 8 + tid4 * 2;
                *(float2*)(out + (size_t)r0 * CC + c0) =
                    make_float2(acc[mi][ni][0] + p.x, acc[mi][ni][1] + p.y);
                *(float2*)(out + (size_t)(r0 + 8) * CC + c0) =
                    make_float2(acc[mi][ni][2] + p.z, acc[mi][ni][3] + p.w);
            }
        }
    }
}

// ---------------------------------------------------------------------------
// Fused tail: 384 blocks = (b,g) x 8 sixteen-row slices.
// Norms from full-K gram diagonals; reduce slice; last block combines in
// fixed order and writes the scalar. Counter self-resets for graph replay.
// ---------------------------------------------------------------------------
__global__ void tail_kernel(float* __restrict__ out) {
    int blk = blockIdx.x;
    int bg  = blk >> 3;
    int q   = blk & 7;          // 16-row slice
    int b   = bg / NG;
    int g   = bg % NG;
    int tid = threadIdx.x;

    const size_t STRIDE = (size_t)BB * NG * CC * CC;
    __shared__ float iA_s[16];
    __shared__ float iB_s[CC];

    int gselA = (g == 0) ? 0 : 1;   // t diag -> gram 0, s diag -> gram 1
    int gselB = (g == 1) ? 1 : 0;

    if (tid < 16) {
        int d = q * 16 + tid;
        const float* base = g_gram + ((size_t)b * NG + gselA) * (CC * CC) + (size_t)d * (CC + 1);
        float v = 0.f;
#pragma unroll
        for (int ks = 0; ks < KSPLIT; ks++) v += base[ks * STRIDE];
        iA_s[tid] = rsqrtf(fmaxf(v, 1e-24f));
    } else if (tid < 16 + CC) {
        int d = tid - 16;
        const float* base = g_gram + ((size_t)b * NG + gselB) * (CC * CC) + (size_t)d * (CC + 1);
        float v = 0.f;
#pragma unroll
        for (int ks = 0; ks < KSPLIT; ks++) v += base[ks * STRIDE];
        iB_s[d] = rsqrtf(fmaxf(v, 1e-24f));
    }
    __syncthreads();

    float w = (g == 2) ? -2.f : 1.f;
    const float* gb = g_gram + ((size_t)b * NG + g) * (CC * CC) + (size_t)q * 16 * CC;

    float lsum = 0.f;
#pragma unroll
    for (int it = 0; it < 2; it++) {
        int e4 = it * 256 + tid;
        float4 v = make_float4(0.f, 0.f, 0.f, 0.f);
#pragma unroll
        for (int ks = 0; ks < KSPLIT; ks++) {
            float4 u = ((const float4*)(gb + ks * STRIDE))[e4];
            v.x += u.x; v.y += u.y; v.z += u.z; v.w += u.w;
        }
        int e = e4 * 4;
        int i = e >> 7;          // local row 0..15
        int j = e & 127;
        float ai = iA_s[i];
        float a0 = v.x * ai * iB_s[j];
        float a1 = v.y * ai * iB_s[j + 1];
        float a2 = v.z * ai * iB_s[j + 2];
        float a3 = v.w * ai * iB_s[j + 3];
        lsum += a0 * a0 + a1 * a1 + a2 * a2 + a3 * a3;
    }

    __shared__ float red[256];
    red[tid] = lsum;
    __syncthreads();
    for (int s = 128; s > 0; s >>= 1) {
        if (tid < s) red[tid] += red[tid + s];
        __syncthreads();
    }

    __shared__ bool is_last;
    if (tid == 0) {
        g_psum[blk] = w * red[0];
        __threadfence();
        int old = atomicAdd(&g_counter, 1);
        is_last = (old == NTAIL - 1);
    }
    __syncthreads();

    if (is_last) {
        __threadfence();
        float s = g_psum[tid] + ((tid < NTAIL - 256) ? g_psum[256 + tid] : 0.f);
        red[tid] = s;
        __syncthreads();
        for (int st = 128; st > 0; st >>= 1) {
            if (tid < st) red[tid] += red[tid + st];
            __syncthreads();
        }
        if (tid == 0) {
            out[0] = red[0] / (float)(BB * CC * CC);
            g_counter = 0;    // reset for next graph replay
        }
    }
}

extern "C" void kernel_launch(void* const* d_in, const int* in_sizes, int n_in,
                              void* d_out, int out_size) {
    const float* fs = (const float*)d_in[0];
    const float* ft = (const float*)d_in[1];
    float* out = (float*)d_out;
    (void)in_sizes; (void)n_in; (void)out_size;

    cudaFuncSetAttribute(gram_kernel,
                         cudaFuncAttributeMaxDynamicSharedMemorySize, DYN_SMEM);

    gram_kernel<<<NJOBS, 256, DYN_SMEM>>>(fs, ft);
    tail_kernel<<<NTAIL, 256>>>(out);
}

// round 14
// speedup vs baseline: 1.7008x; 1.7008x over previous
#include <cuda_runtime.h>
#include <cuda_bf16.h>
#include <cstdint>
#include <math.h>

#define BB 16
#define CC 128
#define TT 16384
#define KSPLIT 8
#define KRANGE (TT / KSPLIT)      // 2048 floats per CTA K-range
#define KT 64                     // K per smem tile (64 bf16 = 128B rows)
#define NKT (KRANGE / KT)         // 32 tiles
#define NG 3
#define NJOBS (BB * NG * KSPLIT)  // 384 CTAs

#define TILE_BYTES 16384          // 128 rows x 64 bf16
#define STAGE_BYTES 32768         // A + B tile
#define DYN_SMEM 65536            // 2 stages

#define NTAIL 384                 // tail blocks: (b,g) x 8 sixteen-row slices

// Scratch (no device allocations allowed -> globals)
__device__ float g_gram[(size_t)KSPLIT * BB * NG * CC * CC];   // 25 MB partials
__device__ float g_psum[NTAIL];
__device__ int   g_counter;       // zero-init; last tail block resets

__device__ __forceinline__ uint32_t smem_u32(const void* p) {
    return (uint32_t)__cvta_generic_to_shared(p);
}
__device__ __forceinline__ uint32_t swz(uint32_t off) {
    return off ^ ((off >> 3) & 0x70);   // SW128 for 128B rows
}
__device__ __forceinline__ void ldsm4(uint32_t& r0, uint32_t& r1, uint32_t& r2,
                                      uint32_t& r3, uint32_t addr) {
    asm volatile("ldmatrix.sync.aligned.m8n8.x4.shared.b16 {%0,%1,%2,%3}, [%4];"
                 : "=r"(r0), "=r"(r1), "=r"(r2), "=r"(r3) : "r"(addr));
}
__device__ __forceinline__ void mma16816(float* c, const uint32_t* a,
                                         uint32_t b0, uint32_t b1) {
    asm volatile(
        "mma.sync.aligned.m16n8k16.row.col.f32.bf16.bf16.f32 "
        "{%0,%1,%2,%3}, {%4,%5,%6,%7}, {%8,%9}, {%0,%1,%2,%3};"
        : "+f"(c[0]), "+f"(c[1]), "+f"(c[2]), "+f"(c[3])
        : "r"(a[0]), "r"(a[1]), "r"(a[2]), "r"(a[3]), "r"(b0), "r"(b1));
}
__device__ __forceinline__ uint2 cvt_bf16x4(float4 v) {
    __nv_bfloat162 lo = __floats2bfloat162_rn(v.x, v.y);
    __nv_bfloat162 hi = __floats2bfloat162_rn(v.z, v.w);
    return make_uint2(*(uint32_t*)&lo, *(uint32_t*)&hi);
}

// ---------------------------------------------------------------------------
// Gram kernel: one CTA per (b, gram, ksplit). 256 threads = 8 warps, all
// homogeneous, each a 32x64 output tile (the measured-best configuration:
// 64 accumulator regs/thread, loads + MMA in every thread, no spills).
// Coalesced loader; raw float4 prefetch held across the MMA loop.
// ---------------------------------------------------------------------------
extern "C" __global__ void __launch_bounds__(256)
gram_kernel(const float* __restrict__ fs, const float* __restrict__ ft) {
    extern __shared__ char smem[];
    const uint32_t smb = smem_u32(smem);

    int bx  = blockIdx.x;
    int b   = bx / (NG * KSPLIT);
    int rem = bx % (NG * KSPLIT);
    int g   = rem / KSPLIT;
    int ks  = rem % KSPLIT;
    bool dual = (g == 2);

    const float* Am = (g == 0) ? ft : fs;
    const float* Bm = (g == 1) ? fs : ft;

    int tid  = threadIdx.x;
    int wid  = tid >> 5;
    int lane = tid & 31;
    int wm   = wid & 3;       // m block: 32*wm
    int wn   = wid >> 2;      // n block: 64*wn
    int gid  = lane >> 2;
    int tid4 = lane & 3;

    // Coalesced loader mapping: 16 lanes cover one contiguous 256B segment.
    int lrow0 = tid >> 4;     // 0..15
    int lcol  = tid & 15;
    const float* baseA = Am + (size_t)b * CC * TT + ks * KRANGE + (size_t)lcol * 4;
    const float* baseB = Bm + (size_t)b * CC * TT + ks * KRANGE + (size_t)lcol * 4;

    // ldmatrix lane addresses
    uint32_t a_row  = (uint32_t)(wm * 32 + (lane & 15));
    uint32_t a_koff = (uint32_t)((lane >> 4) * 16);
    uint32_t b_rowbase = (uint32_t)(wn * 64 + ((lane >> 4) << 3) + (lane & 7));
    uint32_t b_koff = (uint32_t)(((lane >> 3) & 1) * 16);

    float acc[2][8][4];
#pragma unroll
    for (int mi = 0; mi < 2; mi++)
#pragma unroll
        for (int ni = 0; ni < 8; ni++)
#pragma unroll
            for (int q = 0; q < 4; q++) acc[mi][ni][q] = 0.f;

    // ---- prologue: tile 0 ----
    {
#pragma unroll
        for (int i = 0; i < 8; i++) {
            int r = lrow0 + i * 16;
            float4 v = *(const float4*)(baseA + (size_t)r * TT);
            *(uint2*)(smem + swz((uint32_t)r * 128 + lcol * 8)) = cvt_bf16x4(v);
        }
        if (dual) {
#pragma unroll
            for (int i = 0; i < 8; i++) {
                int r = lrow0 + i * 16;
                float4 v = *(const float4*)(baseB + (size_t)r * TT);
                *(uint2*)(smem + TILE_BYTES + swz((uint32_t)r * 128 + lcol * 8)) = cvt_bf16x4(v);
            }
        }
    }
    __syncthreads();

    for (int kt = 0; kt < NKT; kt++) {
        int cur = kt & 1;
        int nxt = cur ^ 1;

        // issue next-tile loads (raw float4, consumed AFTER compute)
        float4 va[8], vb[8];
        if (kt + 1 < NKT) {
            const float* pA = baseA + (size_t)(kt + 1) * KT;
#pragma unroll
            for (int i = 0; i < 8; i++)
                va[i] = *(const float4*)(pA + (size_t)(lrow0 + i * 16) * TT);
            if (dual) {
                const float* pB = baseB + (size_t)(kt + 1) * KT;
#pragma unroll
                for (int i = 0; i < 8; i++)
                    vb[i] = *(const float4*)(pB + (size_t)(lrow0 + i * 16) * TT);
            }
        }

        // compute 4 k16 steps from buffer cur (hides prefetch latency)
        uint32_t abase = smb + cur * STAGE_BYTES;
        uint32_t bbase = abase + (dual ? TILE_BYTES : 0);
#pragma unroll
        for (int kc = 0; kc < 4; kc++) {
            uint32_t kb = (uint32_t)(kc * 32);
            uint32_t afr[2][4];
#pragma unroll
            for (int mi = 0; mi < 2; mi++) {
                uint32_t addr = abase + swz((a_row + mi * 16) * 128 + kb + a_koff);
                ldsm4(afr[mi][0], afr[mi][1], afr[mi][2], afr[mi][3], addr);
            }
#pragma unroll
            for (int nb = 0; nb < 4; nb++) {
                uint32_t r0, r1, r2, r3;
                uint32_t addr = bbase + swz((b_rowbase + nb * 16) * 128 + kb + b_koff);
                ldsm4(r0, r1, r2, r3, addr);
                mma16816(acc[0][2 * nb],     afr[0], r0, r1);
                mma16816(acc[0][2 * nb + 1], afr[0], r2, r3);
                mma16816(acc[1][2 * nb],     afr[1], r0, r1);
                mma16816(acc[1][2 * nb + 1], afr[1], r2, r3);
            }
        }

        // convert + store next tile
        if (kt + 1 < NKT) {
            char* sdst = smem + nxt * STAGE_BYTES;
#pragma unroll
            for (int i = 0; i < 8; i++) {
                uint32_t so = swz((uint32_t)(lrow0 + i * 16) * 128 + lcol * 8);
                *(uint2*)(sdst + so) = cvt_bf16x4(va[i]);
            }
            if (dual) {
#pragma unroll
                for (int i = 0; i < 8; i++) {
                    uint32_t so = swz((uint32_t)(lrow0 + i * 16) * 128 + lcol * 8);
                    *(uint2*)(sdst + TILE_BYTES + so) = cvt_bf16x4(vb[i]);
                }
            }
        }
        __syncthreads();
    }

    // ---- epilogue: partial gram at [i*CC + j] ----
    float* out = g_gram + (((size_t)ks * BB + b) * NG + g) * (CC * CC);
#pragma unroll
    for (int mi = 0; mi < 2; mi++) {
        int r0 = wm * 32 + mi * 16 + gid;
#pragma unroll
        for (int ni = 0; ni < 8; ni++) {
            int c0 = wn * 64 + ni * 8 + tid4 * 2;
            *(float2*)(out + (size_t)r0 * CC + c0) =
                make_float2(acc[mi][ni][0], acc[mi][ni][1]);
            *(float2*)(out + (size_t)(r0 + 8) * CC + c0) =
                make_float2(acc[mi][ni][2], acc[mi][ni][3]);
        }
    }
}

// ---------------------------------------------------------------------------
// Fused tail: 384 blocks = (b,g) x 8 sixteen-row slices. (Measured 11.3us
// at KSPLIT=8.) Norms from full-K gram diagonals; reduce slice; last block
// combines in fixed order and writes the scalar. Counter self-resets.
// ---------------------------------------------------------------------------
__global__ void tail_kernel(float* __restrict__ out) {
    int blk = blockIdx.x;
    int bg  = blk >> 3;
    int q   = blk & 7;          // 16-row slice
    int b   = bg / NG;
    int g   = bg % NG;
    int tid = threadIdx.x;

    const size_t STRIDE = (size_t)BB * NG * CC * CC;
    __shared__ float iA_s[16];
    __shared__ float iB_s[CC];

    int gselA = (g == 0) ? 0 : 1;   // t diag -> gram 0, s diag -> gram 1
    int gselB = (g == 1) ? 1 : 0;

    if (tid < 16) {
        int d = q * 16 + tid;
        const float* base = g_gram + ((size_t)b * NG + gselA) * (CC * CC) + (size_t)d * (CC + 1);
        float v = 0.f;
#pragma unroll
        for (int ks = 0; ks < KSPLIT; ks++) v += base[ks * STRIDE];
        iA_s[tid] = rsqrtf(fmaxf(v, 1e-24f));
    } else if (tid < 16 + CC) {
        int d = tid - 16;
        const float* base = g_gram + ((size_t)b * NG + gselB) * (CC * CC) + (size_t)d * (CC + 1);
        float v = 0.f;
#pragma unroll
        for (int ks = 0; ks < KSPLIT; ks++) v += base[ks * STRIDE];
        iB_s[d] = rsqrtf(fmaxf(v, 1e-24f));
    }
    __syncthreads();

    float w = (g == 2) ? -2.f : 1.f;
    const float* gb = g_gram + ((size_t)b * NG + g) * (CC * CC) + (size_t)q * 16 * CC;

    float lsum = 0.f;
#pragma unroll
    for (int it = 0; it < 2; it++) {
        int e4 = it * 256 + tid;
        float4 v = make_float4(0.f, 0.f, 0.f, 0.f);
#pragma unroll
        for (int ks = 0; ks < KSPLIT; ks++) {
            float4 u = ((const float4*)(gb + ks * STRIDE))[e4];
            v.x += u.x; v.y += u.y; v.z += u.z; v.w += u.w;
        }
        int e = e4 * 4;
        int i = e >> 7;          // local row 0..15
        int j = e & 127;
        float ai = iA_s[i];
        float a0 = v.x * ai * iB_s[j];
        float a1 = v.y * ai * iB_s[j + 1];
        float a2 = v.z * ai * iB_s[j + 2];
        float a3 = v.w * ai * iB_s[j + 3];
        lsum += a0 * a0 + a1 * a1 + a2 * a2 + a3 * a3;
    }

    __shared__ float red[256];
    red[tid] = lsum;
    __syncthreads();
    for (int s = 128; s > 0; s >>= 1) {
        if (tid < s) red[tid] += red[tid + s];
        __syncthreads();
    }

    __shared__ bool is_last;
    if (tid == 0) {
        g_psum[blk] = w * red[0];
        __threadfence();
        int old = atomicAdd(&g_counter, 1);
        is_last = (old == NTAIL - 1);
    }
    __syncthreads();

    if (is_last) {
        __threadfence();
        float s = g_psum[tid] + ((tid < NTAIL - 256) ? g_psum[256 + tid] : 0.f);
        red[tid] = s;
        __syncthreads();
        for (int st = 128; st > 0; st >>= 1) {
            if (tid < st) red[tid] += red[tid + st];
            __syncthreads();
        }
        if (tid == 0) {
            out[0] = red[0] / (float)(BB * CC * CC);
            g_counter = 0;    // reset for next graph replay
        }
    }
}

extern "C" void kernel_launch(void* const* d_in, const int* in_sizes, int n_in,
                              void* d_out, int out_size) {
    const float* fs = (const float*)d_in[0];
    const float* ft = (const float*)d_in[1];
    float* out = (float*)d_out;
    (void)in_sizes; (void)n_in; (void)out_size;

    cudaFuncSetAttribute(gram_kernel,
                         cudaFuncAttributeMaxDynamicSharedMemorySize, DYN_SMEM);

    gram_kernel<<<NJOBS, 256, DYN_SMEM>>>(fs, ft);
    tail_kernel<<<NTAIL, 256>>>(out);
}